// round 13
// baseline (speedup 1.0000x reference)
#include <cuda_runtime.h>
#include <cuda_bf16.h>

// MeanMemoryMessageReducer — segment mean + last timestamp, sorted segment_ids.
//
// 2-kernel pipeline:
//   K1 bounds_scan_v4s : int4 transition scan with sorted-quad fast path
//                        (prev == vals[3] -> whole quad uniform, one compare);
//                        predecessor via __shfl_up (lane 0 only loads scalar)
//   K2 mean_kernel     : warp-per-segment mean (MLP-4 main + predicated MLP-3
//                        tail); lane-0 epilogue AFTER the mainloop
//
// Output layout (float32): [ nids(M) | means(M*128) | last_ts(M) ]

#define DCOLS 128
#define MAX_M (1 << 20)

__device__ int g_bounds[MAX_M + 1];

__global__ __launch_bounds__(256) void bounds_scan_v4s(
    const int* __restrict__ seg, int N, int M)
{
    const int i = blockIdx.x * blockDim.x + threadIdx.x;
    const int base = i * 4;
    const int lane = threadIdx.x & 31;
    const bool active = (base < N);
    const int lim = active ? ((base + 4 <= N) ? 4 : (N - base)) : 0;

    int vals[4] = {0, 0, 0, 0};
    if (lim == 4) {
        const int4 v = *reinterpret_cast<const int4*>(seg + base);
        vals[0] = v.x; vals[1] = v.y; vals[2] = v.z; vals[3] = v.w;
    } else if (active) {
        for (int j = 0; j < lim; ++j) vals[j] = seg[base + j];
        for (int j = lim; j < 4; ++j) vals[j] = vals[lim - 1];
    }

    const int lastv = active ? vals[lim - 1] : 0;
    // All lanes converged: full-mask shuffle is safe.
    const int from_left = __shfl_up_sync(0xffffffffu, lastv, 1);

    if (!active) return;

    int p;
    if (lane == 0) {
        p = (base == 0) ? -1 : seg[base - 1];
    } else {
        p = from_left;   // lane-1 covers [base-4, base); full if this lane active
    }

    const bool is_tail = (base + lim == N);

    // Sorted fast path: seg non-decreasing, so p == vals[3] means the whole
    // quad equals p -> no transitions here; only the tail thread has extra work.
    if (p != vals[lim - 1] || is_tail) {
        #pragma unroll
        for (int j = 0; j < 4; ++j) {
            if (j < lim) {
                const int c = vals[j];
                if (c != p) {
                    const int idx = base + j;
                    g_bounds[c] = idx;              // dominant case: c == p+1
                    for (int s = p + 1; s < c; ++s) // rare: skipped (empty) ids
                        g_bounds[s] = idx;
                    p = c;
                }
            }
        }
        if (is_tail) {
            for (int s = p + 1; s <= M; ++s)
                g_bounds[s] = N;
        }
    }

    if (base == 0) g_bounds[0] = 0;   // s=0: lower_bound is always 0
}

__global__ __launch_bounds__(256) void mean_kernel(
    const float* __restrict__ msgs,
    const int*   __restrict__ nids,
    const float* __restrict__ ts,
    float* __restrict__ out,
    int M, int vec_ok)
{
    const int warp = (int)((blockIdx.x * blockDim.x + threadIdx.x) >> 5);
    const int lane = threadIdx.x & 31;
    if (warp >= M) return;

    const int start = __ldg(&g_bounds[warp]);
    const int end   = __ldg(&g_bounds[warp + 1]);
    const int cnt   = end - start;

    float4 acc = make_float4(0.f, 0.f, 0.f, 0.f);

    if (cnt > 0) {
        // Row = 128 floats = 32 float4; lane l owns columns [4l, 4l+4).
        const float4* p = reinterpret_cast<const float4*>(msgs)
                          + (size_t)start * 32 + lane;
        int n = cnt;

        while (n >= 4) {                 // 4 independent LDG.128 in flight
            float4 a = __ldcs(p);
            float4 b = __ldcs(p + 32);
            float4 c = __ldcs(p + 64);
            float4 d = __ldcs(p + 96);
            acc.x += (a.x + b.x) + (c.x + d.x);
            acc.y += (a.y + b.y) + (c.y + d.y);
            acc.z += (a.z + b.z) + (c.z + d.z);
            acc.w += (a.w + b.w) + (c.w + d.w);
            p += 128;
            n -= 4;
        }

        if (n > 0) {
            // Predicated MLP-3 tail: clamped offsets stay inside the segment,
            // masked rows contribute 0 via FFMA scale.
            const float m1 = (n > 1) ? 1.0f : 0.0f;
            const float m2 = (n > 2) ? 1.0f : 0.0f;
            float4 a = __ldcs(p);
            float4 b = __ldcs(p + ((n > 1) ? 32 : 0));
            float4 c = __ldcs(p + ((n > 2) ? 64 : 0));
            acc.x += a.x + m1 * b.x + m2 * c.x;
            acc.y += a.y + m1 * b.y + m2 * c.y;
            acc.z += a.z + m1 * b.z + m2 * c.z;
            acc.w += a.w + m1 * b.w + m2 * c.w;
        }
    }

    const float inv = 1.0f / fmaxf((float)cnt, 1.0f);
    acc.x *= inv; acc.y *= inv; acc.z *= inv; acc.w *= inv;

    float* ob = out + (size_t)M + (size_t)warp * DCOLS + lane * 4;
    if (vec_ok) {
        __stcs(reinterpret_cast<float4*>(ob), acc);
    } else {
        ob[0] = acc.x; ob[1] = acc.y; ob[2] = acc.z; ob[3] = acc.w;
    }

    // Lane-0 epilogue after the mainloop: nid cast + last timestamp
    // (reference clips the empty-segment index to 0).
    if (lane == 0) {
        out[warp] = (float)nids[warp];
        const int idx = (cnt > 0) ? (end - 1) : 0;
        out[(size_t)M * (DCOLS + 1) + warp] = ts[idx];
    }
}

extern "C" void kernel_launch(void* const* d_in, const int* in_sizes, int n_in,
                              void* d_out, int out_size)
{
    const int*   nids = (const int*)d_in[0];
    const float* msgs = (const float*)d_in[1];
    const float* ts   = (const float*)d_in[2];
    const int*   seg  = (const int*)d_in[3];
    float* out = (float*)d_out;

    const int M = in_sizes[0];
    const int N = in_sizes[2];
    const int vec_ok = ((M & 3) == 0) ? 1 : 0;   // out+M 16B-aligned

    const int n4 = (N + 3) / 4;
    bounds_scan_v4s<<<(n4 + 255) / 256, 256>>>(seg, N, M);

    const long long threads = (long long)M * 32;
    mean_kernel<<<(unsigned)((threads + 255) / 256), 256>>>(
        msgs, nids, ts, out, M, vec_ok);
}

// round 14
// speedup vs baseline: 1.0262x; 1.0262x over previous
#include <cuda_runtime.h>
#include <cuda_bf16.h>

// MeanMemoryMessageReducer — segment mean + last timestamp, sorted segment_ids.
//
// 2-kernel pipeline (measured-best combination, R12 revert):
//   K1 bounds_scan_v4s : int4 transition scan, 4 elems/thread; predecessor via
//                        __shfl_up (lane 0 only does the scalar load)
//   K2 mean_kernel     : warp-per-segment mean (MLP-4 main + predicated MLP-3
//                        tail); lane-0 epilogue AFTER the mainloop
//
// Output layout (float32): [ nids(M) | means(M*128) | last_ts(M) ]

#define DCOLS 128
#define MAX_M (1 << 20)

__device__ int g_bounds[MAX_M + 1];

__global__ __launch_bounds__(256) void bounds_scan_v4s(
    const int* __restrict__ seg, int N, int M)
{
    const int i = blockIdx.x * blockDim.x + threadIdx.x;
    const int base = i * 4;
    const int lane = threadIdx.x & 31;
    const bool active = (base < N);
    const int lim = active ? ((base + 4 <= N) ? 4 : (N - base)) : 0;

    int vals[4] = {0, 0, 0, 0};
    if (lim == 4) {
        const int4 v = *reinterpret_cast<const int4*>(seg + base);
        vals[0] = v.x; vals[1] = v.y; vals[2] = v.z; vals[3] = v.w;
    } else if (active) {
        for (int j = 0; j < lim; ++j) vals[j] = seg[base + j];
    }

    const int lastv = active ? vals[lim - 1] : 0;
    // All lanes converged: full-mask shuffle is safe.
    const int from_left = __shfl_up_sync(0xffffffffu, lastv, 1);

    if (!active) return;

    int p;
    if (lane == 0) {
        p = (base == 0) ? -1 : seg[base - 1];
    } else {
        p = from_left;   // lane-1 covers [base-4, base); full if this lane active
    }

    #pragma unroll
    for (int j = 0; j < 4; ++j) {
        if (j < lim) {
            const int c = vals[j];
            for (int s = p + 1; s <= c; ++s)
                g_bounds[s] = base + j;
            p = c;
        }
    }

    if (base + lim == N) {               // thread owning the final element
        for (int s = p + 1; s <= M; ++s)
            g_bounds[s] = N;
    }
}

__global__ __launch_bounds__(256) void mean_kernel(
    const float* __restrict__ msgs,
    const int*   __restrict__ nids,
    const float* __restrict__ ts,
    float* __restrict__ out,
    int M, int vec_ok)
{
    const int warp = (int)((blockIdx.x * blockDim.x + threadIdx.x) >> 5);
    const int lane = threadIdx.x & 31;
    if (warp >= M) return;

    const int start = __ldg(&g_bounds[warp]);
    const int end   = __ldg(&g_bounds[warp + 1]);
    const int cnt   = end - start;

    float4 acc = make_float4(0.f, 0.f, 0.f, 0.f);

    if (cnt > 0) {
        // Row = 128 floats = 32 float4; lane l owns columns [4l, 4l+4).
        const float4* p = reinterpret_cast<const float4*>(msgs)
                          + (size_t)start * 32 + lane;
        int n = cnt;

        while (n >= 4) {                 // 4 independent LDG.128 in flight
            float4 a = __ldcs(p);
            float4 b = __ldcs(p + 32);
            float4 c = __ldcs(p + 64);
            float4 d = __ldcs(p + 96);
            acc.x += (a.x + b.x) + (c.x + d.x);
            acc.y += (a.y + b.y) + (c.y + d.y);
            acc.z += (a.z + b.z) + (c.z + d.z);
            acc.w += (a.w + b.w) + (c.w + d.w);
            p += 128;
            n -= 4;
        }

        if (n > 0) {
            // Predicated MLP-3 tail: clamped offsets stay inside the segment,
            // masked rows contribute 0 via FFMA scale.
            const float m1 = (n > 1) ? 1.0f : 0.0f;
            const float m2 = (n > 2) ? 1.0f : 0.0f;
            float4 a = __ldcs(p);
            float4 b = __ldcs(p + ((n > 1) ? 32 : 0));
            float4 c = __ldcs(p + ((n > 2) ? 64 : 0));
            acc.x += a.x + m1 * b.x + m2 * c.x;
            acc.y += a.y + m1 * b.y + m2 * c.y;
            acc.z += a.z + m1 * b.z + m2 * c.z;
            acc.w += a.w + m1 * b.w + m2 * c.w;
        }
    }

    const float inv = 1.0f / fmaxf((float)cnt, 1.0f);
    acc.x *= inv; acc.y *= inv; acc.z *= inv; acc.w *= inv;

    float* ob = out + (size_t)M + (size_t)warp * DCOLS + lane * 4;
    if (vec_ok) {
        __stcs(reinterpret_cast<float4*>(ob), acc);
    } else {
        ob[0] = acc.x; ob[1] = acc.y; ob[2] = acc.z; ob[3] = acc.w;
    }

    // Lane-0 epilogue after the mainloop: nid cast + last timestamp
    // (reference clips the empty-segment index to 0).
    if (lane == 0) {
        out[warp] = (float)nids[warp];
        const int idx = (cnt > 0) ? (end - 1) : 0;
        out[(size_t)M * (DCOLS + 1) + warp] = ts[idx];
    }
}

extern "C" void kernel_launch(void* const* d_in, const int* in_sizes, int n_in,
                              void* d_out, int out_size)
{
    const int*   nids = (const int*)d_in[0];
    const float* msgs = (const float*)d_in[1];
    const float* ts   = (const float*)d_in[2];
    const int*   seg  = (const int*)d_in[3];
    float* out = (float*)d_out;

    const int M = in_sizes[0];
    const int N = in_sizes[2];
    const int vec_ok = ((M & 3) == 0) ? 1 : 0;   // out+M 16B-aligned

    const int n4 = (N + 3) / 4;
    bounds_scan_v4s<<<(n4 + 255) / 256, 256>>>(seg, N, M);

    const long long threads = (long long)M * 32;
    mean_kernel<<<(unsigned)((threads + 255) / 256), 256>>>(
        msgs, nids, ts, out, M, vec_ok);
}

// round 15
// speedup vs baseline: 1.0364x; 1.0099x over previous
#include <cuda_runtime.h>
#include <cuda_bf16.h>

// MeanMemoryMessageReducer — segment mean + last timestamp, sorted segment_ids.
//
// 2-kernel pipeline with PDL overlap:
//   K1 bounds_scan_v4s : int4 transition scan; predecessor via __shfl_up;
//                        fires cudaTriggerProgrammaticLaunchCompletion after
//                        its final g_bounds write.
//   K2 mean_kernel     : launched with PROGRAMMATIC_STREAM_SERIALIZATION so its
//                        block ramp + bounds-independent prologue overlap K1;
//                        cudaGridDependencySynchronize() guards the first
//                        g_bounds read. Mainloop: MLP-4 + predicated MLP-3
//                        tail; lane-0 epilogue after the mainloop.
//
// Output layout (float32): [ nids(M) | means(M*128) | last_ts(M) ]

#define DCOLS 128
#define MAX_M (1 << 20)

__device__ int g_bounds[MAX_M + 1];

__global__ __launch_bounds__(256) void bounds_scan_v4s(
    const int* __restrict__ seg, int N, int M)
{
    const int i = blockIdx.x * blockDim.x + threadIdx.x;
    const int base = i * 4;
    const int lane = threadIdx.x & 31;
    const bool active = (base < N);
    const int lim = active ? ((base + 4 <= N) ? 4 : (N - base)) : 0;

    int vals[4] = {0, 0, 0, 0};
    if (lim == 4) {
        const int4 v = *reinterpret_cast<const int4*>(seg + base);
        vals[0] = v.x; vals[1] = v.y; vals[2] = v.z; vals[3] = v.w;
    } else if (active) {
        for (int j = 0; j < lim; ++j) vals[j] = seg[base + j];
    }

    const int lastv = active ? vals[lim - 1] : 0;
    // All lanes converged: full-mask shuffle is safe.
    const int from_left = __shfl_up_sync(0xffffffffu, lastv, 1);

    if (active) {
        int p;
        if (lane == 0) {
            p = (base == 0) ? -1 : seg[base - 1];
        } else {
            p = from_left;   // lane-1 covers [base-4, base)
        }

        #pragma unroll
        for (int j = 0; j < 4; ++j) {
            if (j < lim) {
                const int c = vals[j];
                for (int s = p + 1; s <= c; ++s)
                    g_bounds[s] = base + j;
                p = c;
            }
        }

        if (base + lim == N) {           // thread owning the final element
            for (int s = p + 1; s <= M; ++s)
                g_bounds[s] = N;
        }
    }

#if __CUDA_ARCH__ >= 900
    // All g_bounds writes for this thread are done; allow the dependent
    // mean_kernel launch to proceed.
    cudaTriggerProgrammaticLaunchCompletion();
#endif
}

__global__ __launch_bounds__(256) void mean_kernel(
    const float* __restrict__ msgs,
    const int*   __restrict__ nids,
    const float* __restrict__ ts,
    float* __restrict__ out,
    int M, int vec_ok)
{
    const int warp = (int)((blockIdx.x * blockDim.x + threadIdx.x) >> 5);
    const int lane = threadIdx.x & 31;

    // ---- bounds-independent prologue (overlaps K1 under PDL) ----
    float nid_f = 0.0f;
    if (warp < M && lane == 0)
        nid_f = (float)__ldg(&nids[warp]);   // load issued before the sync

#if __CUDA_ARCH__ >= 900
    cudaGridDependencySynchronize();         // wait for K1's g_bounds writes
#endif

    if (warp >= M) return;

    const int start = __ldg(&g_bounds[warp]);
    const int end   = __ldg(&g_bounds[warp + 1]);
    const int cnt   = end - start;

    float4 acc = make_float4(0.f, 0.f, 0.f, 0.f);

    if (cnt > 0) {
        // Row = 128 floats = 32 float4; lane l owns columns [4l, 4l+4).
        const float4* p = reinterpret_cast<const float4*>(msgs)
                          + (size_t)start * 32 + lane;
        int n = cnt;

        while (n >= 4) {                 // 4 independent LDG.128 in flight
            float4 a = __ldcs(p);
            float4 b = __ldcs(p + 32);
            float4 c = __ldcs(p + 64);
            float4 d = __ldcs(p + 96);
            acc.x += (a.x + b.x) + (c.x + d.x);
            acc.y += (a.y + b.y) + (c.y + d.y);
            acc.z += (a.z + b.z) + (c.z + d.z);
            acc.w += (a.w + b.w) + (c.w + d.w);
            p += 128;
            n -= 4;
        }

        if (n > 0) {
            // Predicated MLP-3 tail: clamped offsets stay inside the segment,
            // masked rows contribute 0 via FFMA scale.
            const float m1 = (n > 1) ? 1.0f : 0.0f;
            const float m2 = (n > 2) ? 1.0f : 0.0f;
            float4 a = __ldcs(p);
            float4 b = __ldcs(p + ((n > 1) ? 32 : 0));
            float4 c = __ldcs(p + ((n > 2) ? 64 : 0));
            acc.x += a.x + m1 * b.x + m2 * c.x;
            acc.y += a.y + m1 * b.y + m2 * c.y;
            acc.z += a.z + m1 * b.z + m2 * c.z;
            acc.w += a.w + m1 * b.w + m2 * c.w;
        }
    }

    const float inv = 1.0f / fmaxf((float)cnt, 1.0f);
    acc.x *= inv; acc.y *= inv; acc.z *= inv; acc.w *= inv;

    float* ob = out + (size_t)M + (size_t)warp * DCOLS + lane * 4;
    if (vec_ok) {
        __stcs(reinterpret_cast<float4*>(ob), acc);
    } else {
        ob[0] = acc.x; ob[1] = acc.y; ob[2] = acc.z; ob[3] = acc.w;
    }

    // Lane-0 epilogue after the mainloop: nid cast + last timestamp
    // (reference clips the empty-segment index to 0).
    if (lane == 0) {
        out[warp] = nid_f;
        const int idx = (cnt > 0) ? (end - 1) : 0;
        out[(size_t)M * (DCOLS + 1) + warp] = ts[idx];
    }
}

extern "C" void kernel_launch(void* const* d_in, const int* in_sizes, int n_in,
                              void* d_out, int out_size)
{
    const int*   nids = (const int*)d_in[0];
    const float* msgs = (const float*)d_in[1];
    const float* ts   = (const float*)d_in[2];
    const int*   seg  = (const int*)d_in[3];
    float* out = (float*)d_out;

    const int M = in_sizes[0];
    const int N = in_sizes[2];
    const int vec_ok = ((M & 3) == 0) ? 1 : 0;   // out+M 16B-aligned

    const int n4 = (N + 3) / 4;
    bounds_scan_v4s<<<(n4 + 255) / 256, 256>>>(seg, N, M);

    // K2 with programmatic dependent launch: overlaps K1's tail.
    const long long threads = (long long)M * 32;
    const unsigned grid2 = (unsigned)((threads + 255) / 256);

    cudaLaunchConfig_t cfg = {};
    cfg.gridDim  = dim3(grid2, 1, 1);
    cfg.blockDim = dim3(256, 1, 1);
    cfg.dynamicSmemBytes = 0;
    cfg.stream = 0;   // legacy default stream (the captured stream context)

    cudaLaunchAttribute attrs[1];
    attrs[0].id = cudaLaunchAttributeProgrammaticStreamSerialization;
    attrs[0].val.programmaticStreamSerializationAllowed = 1;
    cfg.attrs = attrs;
    cfg.numAttrs = 1;

    cudaError_t err = cudaLaunchKernelEx(&cfg, mean_kernel,
                                         msgs, nids, ts, out, M, vec_ok);
    if (err != cudaSuccess) {
        // Fallback: plain launch (still correct, just no overlap).
        mean_kernel<<<grid2, 256>>>(msgs, nids, ts, out, M, vec_ok);
    }
}